// round 10
// baseline (speedup 1.0000x reference)
#include <cuda_runtime.h>
#include <math.h>
#include <stdint.h>

#define SLEN   2048
#define DHEAD  64
#define NGROUP 32
#define MROWS  8192
#define DMODEL 512
#define QK_SCALE 0.04419417382415922f   // 1/sqrt(512)

// Scratch
__device__ float g_Qhl[(size_t)2 * MROWS * DMODEL];  // interleaved {hi,lo}, pre-scaled
__device__ float g_Khl[(size_t)2 * MROWS * DMODEL];  // interleaved {hi,lo}
__device__ float g_Vp [(size_t)MROWS * DMODEL];      // pair-transposed tf32 (see below)
__device__ float g_Ohl[(size_t)2 * MROWS * DMODEL];  // interleaved {hi,lo}
__device__ float g_Ksum[NGROUP * DHEAD];

__device__ __forceinline__ uint32_t f32_to_tf32(float x) {
    uint32_t r;
    asm("cvt.rna.tf32.f32 %0, %1;" : "=r"(r) : "f"(x));
    return r;
}
__device__ __forceinline__ float tf32f(float x) {
    return __uint_as_float(f32_to_tf32(x));
}
__device__ __forceinline__ void mma_tf32(float (&c)[4],
    uint32_t a0, uint32_t a1, uint32_t a2, uint32_t a3,
    uint32_t b0, uint32_t b1)
{
    asm volatile(
        "mma.sync.aligned.m16n8k8.row.col.f32.tf32.tf32.f32 "
        "{%0,%1,%2,%3}, {%4,%5,%6,%7}, {%8,%9}, {%0,%1,%2,%3};\n"
        : "+f"(c[0]), "+f"(c[1]), "+f"(c[2]), "+f"(c[3])
        : "r"(a0), "r"(a1), "r"(a2), "r"(a3), "r"(b0), "r"(b1));
}

// ---------------------------------------------------------------------------
// fp32 FFMA SGEMM (round-1 proven core) for Q and K projections (EXACT fp32).
// MODE 0 (Q): t *= QK_SCALE, write interleaved {hi,lo}; block(0,0) zeroes Ksum.
// MODE 1 (K): write interleaved {hi,lo} + fused exact column-sum -> Ksum.
// 128x128 tile, BK=8, 256 threads, 8x8 microtile.
// ---------------------------------------------------------------------------
template<int MODE>
__global__ __launch_bounds__(256) void sgemm_qk(
    const float* __restrict__ A, const float* __restrict__ W,
    const float* __restrict__ bias, float* __restrict__ C,
    float* __restrict__ Ksum)
{
    __shared__ float As[8][128];
    __shared__ float Bs[8][128];
    __shared__ float s_cs[128];

    const int tid = threadIdx.x;
    const int bx = blockIdx.x, by = blockIdx.y;
    const float* Ab = A + (size_t)by * 128 * DMODEL;
    const float* Bb = W + bx * 128;

    const int arow = tid >> 1, acol = (tid & 1) * 4;
    const int brow = tid >> 5, bcol = (tid & 31) * 4;
    const int ty = tid >> 4, tx = tid & 15;

    if (MODE == 0 && bx == 0 && by == 0) {
        for (int i = tid; i < NGROUP * DHEAD; i += 256) Ksum[i] = 0.f;
    }
    if (MODE == 1 && tid < 128) s_cs[tid] = 0.f;

    float acc[8][8] = {};

    for (int k0 = 0; k0 < DMODEL; k0 += 8) {
        float4 av = *(const float4*)(Ab + (size_t)arow * DMODEL + k0 + acol);
        As[acol + 0][arow] = av.x;
        As[acol + 1][arow] = av.y;
        As[acol + 2][arow] = av.z;
        As[acol + 3][arow] = av.w;
        *(float4*)&Bs[brow][bcol] =
            *(const float4*)(Bb + (size_t)(k0 + brow) * DMODEL + bcol);
        __syncthreads();

        #pragma unroll
        for (int k = 0; k < 8; k++) {
            float a[8], b[8];
            *(float4*)&a[0] = *(float4*)&As[k][ty * 8];
            *(float4*)&a[4] = *(float4*)&As[k][ty * 8 + 4];
            *(float4*)&b[0] = *(float4*)&Bs[k][tx * 8];
            *(float4*)&b[4] = *(float4*)&Bs[k][tx * 8 + 4];
            #pragma unroll
            for (int i = 0; i < 8; i++)
                #pragma unroll
                for (int j = 0; j < 8; j++)
                    acc[i][j] += a[i] * b[j];
        }
        __syncthreads();
    }

    float cs[8];
    if (MODE == 1)
        #pragma unroll
        for (int j = 0; j < 8; j++) cs[j] = 0.f;

    #pragma unroll
    for (int i = 0; i < 8; i++) {
        int row = by * 128 + ty * 8 + i;
        #pragma unroll
        for (int j = 0; j < 8; j += 2) {
            int c = bx * 128 + tx * 8 + j;
            float t0 = acc[i][j]     + bias[c];
            float t1 = acc[i][j + 1] + bias[c + 1];
            if (MODE == 1) { cs[j] += t0; cs[j + 1] += t1; }
            if (MODE == 0) { t0 *= QK_SCALE; t1 *= QK_SCALE; }
            float h0 = tf32f(t0), h1 = tf32f(t1);
            *(float4*)(C + 2 * ((size_t)row * DMODEL + c)) =
                make_float4(h0, tf32f(t0 - h0), h1, tf32f(t1 - h1));
        }
    }

    if (MODE == 1) {
        #pragma unroll
        for (int j = 0; j < 8; j++)
            atomicAdd(&s_cs[tx * 8 + j], cs[j]);
        __syncthreads();
        if (tid < 128)
            atomicAdd(&Ksum[(by >> 1) * 64 + (tid & 63)], s_cs[tid]);
    }
}

// ---------------------------------------------------------------------------
// 3xtf32 GEMM for V and O projections.
// AHL=0: A fp32 (split at load); AHL=1: A interleaved hi/lo.
// MODE 0: fp32 out.
// MODE 4: V pair-transposed tf32 out:
//   element (key k, d) of group g stored at
//   g*131072 + (k>>7)*8192 + d*128 + ((k&127)>>3)*8 + (k&3)*2 + ((k>>2)&1)
//   => per 128-key tile layout [d][keypair] with k,k+4 adjacent.
// ---------------------------------------------------------------------------
#define AS 133
#define BS 37
#define GEMM_SMEM_FLOATS (2 * 32 * AS + 2 * 128 * BS)
#define GEMM_SMEM_BYTES  (GEMM_SMEM_FLOATS * 4)

template<int MODE, int AHL>
__global__ __launch_bounds__(256, 2) void gemm_t(
    const float* __restrict__ A, const float* __restrict__ W,
    const float* __restrict__ bias, float* __restrict__ C)
{
    extern __shared__ float gsm[];
    float* AhiT = gsm;                       // [32][133]
    float* AloT = AhiT + 32 * AS;
    float* Bhi  = AloT + 32 * AS;            // [128][37]
    float* Blo  = Bhi + 128 * BS;

    const int tid = threadIdx.x;
    const int bx = blockIdx.x, by = blockIdx.y;
    const int warp = tid >> 5, lane = tid & 31;
    const int wm = warp >> 2, wn = warp & 3;
    const int lg = lane >> 2, la = lane & 3;

    float acc[4][4][4] = {};

    for (int k0 = 0; k0 < DMODEL; k0 += 32) {
        #pragma unroll
        for (int l = 0; l < 16; l++) {
            int idx = tid + l * 256;
            int r = idx >> 5, k = idx & 31;
            if (AHL) {
                float2 v = *(const float2*)(A +
                    2 * ((size_t)(by * 128 + r) * DMODEL + k0 + k));
                AhiT[k * AS + r] = v.x;
                AloT[k * AS + r] = v.y;
            } else {
                float v = A[(size_t)(by * 128 + r) * DMODEL + k0 + k];
                float h = tf32f(v);
                AhiT[k * AS + r] = h;
                AloT[k * AS + r] = tf32f(v - h);
            }
        }
        #pragma unroll
        for (int l = 0; l < 16; l++) {
            int idx = tid + l * 256;
            int k = idx >> 7, n = idx & 127;
            float b = W[(size_t)(k0 + k) * DMODEL + bx * 128 + n];
            float h = tf32f(b);
            Bhi[n * BS + k] = h;
            Blo[n * BS + k] = tf32f(b - h);
        }
        __syncthreads();

        #pragma unroll
        for (int kk = 0; kk < 4; kk++) {
            uint32_t ahi[4][4], alo[4][4];
            #pragma unroll
            for (int mf = 0; mf < 4; mf++) {
                int r0 = wm * 64 + mf * 16 + lg;
                int c0 = kk * 8 + la;
                ahi[mf][0] = __float_as_uint(AhiT[c0 * AS + r0]);
                ahi[mf][1] = __float_as_uint(AhiT[c0 * AS + r0 + 8]);
                ahi[mf][2] = __float_as_uint(AhiT[(c0 + 4) * AS + r0]);
                ahi[mf][3] = __float_as_uint(AhiT[(c0 + 4) * AS + r0 + 8]);
                alo[mf][0] = __float_as_uint(AloT[c0 * AS + r0]);
                alo[mf][1] = __float_as_uint(AloT[c0 * AS + r0 + 8]);
                alo[mf][2] = __float_as_uint(AloT[(c0 + 4) * AS + r0]);
                alo[mf][3] = __float_as_uint(AloT[(c0 + 4) * AS + r0 + 8]);
            }
            #pragma unroll
            for (int nf = 0; nf < 4; nf++) {
                int n = wn * 32 + nf * 8 + lg;
                int c0 = kk * 8 + la;
                uint32_t bhi0 = __float_as_uint(Bhi[n * BS + c0]);
                uint32_t bhi1 = __float_as_uint(Bhi[n * BS + c0 + 4]);
                uint32_t blo0 = __float_as_uint(Blo[n * BS + c0]);
                uint32_t blo1 = __float_as_uint(Blo[n * BS + c0 + 4]);
                #pragma unroll
                for (int mf = 0; mf < 4; mf++) {
                    mma_tf32(acc[mf][nf], ahi[mf][0], ahi[mf][1], ahi[mf][2], ahi[mf][3], bhi0, bhi1);
                    mma_tf32(acc[mf][nf], alo[mf][0], alo[mf][1], alo[mf][2], alo[mf][3], bhi0, bhi1);
                    mma_tf32(acc[mf][nf], ahi[mf][0], ahi[mf][1], ahi[mf][2], ahi[mf][3], blo0, blo1);
                }
            }
        }
        __syncthreads();
    }

    #pragma unroll
    for (int mf = 0; mf < 4; mf++) {
        #pragma unroll
        for (int h = 0; h < 2; h++) {
            int r = by * 128 + wm * 64 + mf * 16 + lg + h * 8;
            #pragma unroll
            for (int nf = 0; nf < 4; nf++) {
                int c = bx * 128 + wn * 32 + nf * 8 + 2 * la;
                float t0 = acc[mf][nf][2 * h + 0] + bias[c];
                float t1 = acc[mf][nf][2 * h + 1] + bias[c + 1];
                if (MODE == 0) {
                    *(float2*)(C + (size_t)r * DMODEL + c) = make_float2(t0, t1);
                } else {
                    int g  = r >> 8;
                    int kr = ((r & 255) << 3) + (c >> 6);
                    int d  = c & 63;
                    size_t base = (size_t)g * 131072 + (size_t)(kr >> 7) * 8192
                                + (size_t)d * 128;
                    int pi2 = (((kr & 127) >> 3) << 3) + ((kr & 3) << 1) + ((kr >> 2) & 1);
                    C[base + pi2]       = tf32f(t0);
                    C[base + 128 + pi2] = tf32f(t1);   // d+1
                }
            }
        }
    }
}

// ---------------------------------------------------------------------------
// Fused attention v5 (v4 + paired V + tf32 P): 512 thr / 16 warps.
// warp = (q-strip wq: 16 rows) x (key-half wk: 64 keys) for S;
//        (q-strip) x (32 d-cols) over all 128 keys for PV.
// Qs, KP: [128][136] interleaved hi/lo (KP reused for tf32 P).
// Vs: pair-transposed [64 d][136] — PV B-frag = ONE conflict-free LDS.64.
// ---------------------------------------------------------------------------
#define QKS 136
#define VTS 136
#define FUSED_SMEM ((2 * 128 * QKS + 64 * VTS + 64 + 128 + 256) * 4)

__global__ __launch_bounds__(512, 1) void fused_attn(
    const float* __restrict__ Qhl, const float* __restrict__ Khl,
    const float* __restrict__ Vp, const float* __restrict__ Ksum,
    float* __restrict__ Ohl)
{
    extern __shared__ float sm[];
    float* Qs     = sm;                    // [128][136]
    float* KP     = Qs + 128 * QKS;        // [128][136] K tile, then tf32 P
    float* Vs     = KP + 128 * QKS;        // [64][136] pair-transposed
    float* s_ksum = Vs + 64 * VTS;         // 64
    float* s_mean = s_ksum + 64;           // 128
    float* zsm    = s_mean + 128;          // 256

    const int tid = threadIdx.x;
    const int lane = tid & 31, warp = tid >> 5;
    const int wq = warp >> 1, wk = warp & 1;
    const int lg = lane >> 2, la = lane & 3;
    const int g = blockIdx.y, qt = blockIdx.x;

    const float* Qg = Qhl + 2 * ((size_t)(g * SLEN + qt * 128)) * DHEAD;
    const float* Kg = Khl + 2 * (size_t)g * SLEN * DHEAD;
    const float* Vg = Vp + (size_t)g * SLEN * DHEAD;

    #pragma unroll
    for (int l = 0; l < 8; l++) {
        int idx = tid + l * 512;
        int r = idx >> 5, c = (idx & 31) * 4;
        *(float4*)(Qs + r * QKS + c) = *(const float4*)(Qg + (size_t)r * 128 + c);
    }
    if (tid < 64) s_ksum[tid] = Ksum[g * 64 + tid];
    __syncthreads();
    if (tid < 128) {
        float a = 0.f;
        #pragma unroll
        for (int d = 0; d < 64; d++)
            a += (Qs[tid * QKS + 2 * d] + Qs[tid * QKS + 2 * d + 1]) * s_ksum[d];
        s_mean[tid] = a * (1.0f / 2048.0f);
    }
    __syncthreads();

    const int r0 = wq * 16 + lg;
    const float m0 = s_mean[r0], m1 = s_mean[r0 + 8];

    float oacc[4][4] = {};
    float z0 = 0.f, z1 = 0.f;

    for (int kt = 0; kt < 16; kt++) {
        // K tile: 4096 float4 (8/thr); V tile (paired layout): 2048 float4 (4/thr)
        #pragma unroll
        for (int l = 0; l < 8; l++) {
            int idx = tid + l * 512;
            int r = idx >> 5, c = (idx & 31) * 4;
            *(float4*)(KP + r * QKS + c) =
                *(const float4*)(Kg + (size_t)(kt * 128 + r) * 128 + c);
        }
        #pragma unroll
        for (int l = 0; l < 4; l++) {
            int idx = tid + l * 512;
            int d = idx >> 5, c = (idx & 31) * 4;
            *(float4*)(Vs + d * VTS + c) =
                *(const float4*)(Vg + (size_t)kt * 8192 + (size_t)idx * 4);
        }
        __syncthreads();

        // === S = Q @ K^T (3xtf32): warp = 16 q-rows x 64 keys ===
        float sc[8][4];
        #pragma unroll
        for (int nf = 0; nf < 8; nf++)
            #pragma unroll
            for (int j = 0; j < 4; j++) sc[nf][j] = 0.f;

        #pragma unroll
        for (int kk = 0; kk < 8; kk++) {
            int c2 = 2 * (kk * 8 + la);
            float2 q0 = *(const float2*)(Qs + r0 * QKS + c2);
            float2 q1 = *(const float2*)(Qs + (r0 + 8) * QKS + c2);
            float2 q2 = *(const float2*)(Qs + r0 * QKS + c2 + 8);
            float2 q3 = *(const float2*)(Qs + (r0 + 8) * QKS + c2 + 8);
            uint32_t qh0 = __float_as_uint(q0.x), ql0 = __float_as_uint(q0.y);
            uint32_t qh1 = __float_as_uint(q1.x), ql1 = __float_as_uint(q1.y);
            uint32_t qh2 = __float_as_uint(q2.x), ql2 = __float_as_uint(q2.y);
            uint32_t qh3 = __float_as_uint(q3.x), ql3 = __float_as_uint(q3.y);
            #pragma unroll
            for (int nf = 0; nf < 8; nf++) {
                int kr = wk * 64 + nf * 8 + lg;
                float2 b0 = *(const float2*)(KP + kr * QKS + c2);
                float2 b1 = *(const float2*)(KP + kr * QKS + c2 + 8);
                uint32_t bh0 = __float_as_uint(b0.x), bh1 = __float_as_uint(b1.x);
                uint32_t bl0 = __float_as_uint(b0.y), bl1 = __float_as_uint(b1.y);
                mma_tf32(sc[nf], qh0, qh1, qh2, qh3, bh0, bh1);
                mma_tf32(sc[nf], ql0, ql1, ql2, ql3, bh0, bh1);
                mma_tf32(sc[nf], qh0, qh1, qh2, qh3, bl0, bl1);
            }
        }
        __syncthreads();

        // === mask + exp; tf32 P into KP; Z from fp32 p ===
        #pragma unroll
        for (int nf = 0; nf < 8; nf++) {
            int col = wk * 64 + nf * 8 + 2 * la;
            float p0 = (sc[nf][0] > m0) ? __expf(sc[nf][0]) : 0.f;
            float p1 = (sc[nf][1] > m0) ? __expf(sc[nf][1]) : 0.f;
            float p2 = (sc[nf][2] > m1) ? __expf(sc[nf][2]) : 0.f;
            float p3 = (sc[nf][3] > m1) ? __expf(sc[nf][3]) : 0.f;
            z0 += p0 + p1; z1 += p2 + p3;
            *(float2*)(KP + r0 * QKS + col)       = make_float2(tf32f(p0), tf32f(p1));
            *(float2*)(KP + (r0 + 8) * QKS + col) = make_float2(tf32f(p2), tf32f(p3));
        }
        __syncthreads();

        // === O += P @ V: warp = q-strip x 32 d-cols, all 128 keys ===
        #pragma unroll
        for (int kk = 0; kk < 16; kk++) {
            int c0 = kk * 8 + la;
            uint32_t a0 = __float_as_uint(KP[r0 * QKS + c0]);
            uint32_t a1 = __float_as_uint(KP[(r0 + 8) * QKS + c0]);
            uint32_t a2 = __float_as_uint(KP[r0 * QKS + c0 + 4]);
            uint32_t a3 = __float_as_uint(KP[(r0 + 8) * QKS + c0 + 4]);
            int vp2 = (kk * 4 + la) * 2;
            #pragma unroll
            for (int nf = 0; nf < 4; nf++) {
                int vc = wk * 32 + nf * 8 + lg;
                float2 bv = *(const float2*)(Vs + vc * VTS + vp2);
                mma_tf32(oacc[nf], a0, a1, a2, a3,
                         __float_as_uint(bv.x), __float_as_uint(bv.y));
            }
        }
        __syncthreads();
    }

    z0 += __shfl_xor_sync(0xffffffffu, z0, 1);
    z0 += __shfl_xor_sync(0xffffffffu, z0, 2);
    z1 += __shfl_xor_sync(0xffffffffu, z1, 1);
    z1 += __shfl_xor_sync(0xffffffffu, z1, 2);
    if (la == 0) {
        zsm[r0 * 2 + wk]       = z0;
        zsm[(r0 + 8) * 2 + wk] = z1;
    }
    __syncthreads();
    const float iz0 = 1.f / (zsm[r0 * 2] + zsm[r0 * 2 + 1]);
    const float iz1 = 1.f / (zsm[(r0 + 8) * 2] + zsm[(r0 + 8) * 2 + 1]);

    float* Og = Ohl + 2 * ((size_t)(g * SLEN + qt * 128)) * DHEAD;
    #pragma unroll
    for (int nf = 0; nf < 4; nf++) {
        int c2 = 2 * (wk * 32 + nf * 8 + 2 * la);
        float t0 = oacc[nf][0] * iz0, t1 = oacc[nf][1] * iz0;
        float h0 = tf32f(t0), h1 = tf32f(t1);
        *(float4*)(Og + (size_t)r0 * 128 + c2) =
            make_float4(h0, tf32f(t0 - h0), h1, tf32f(t1 - h1));
        float t2 = oacc[nf][2] * iz1, t3 = oacc[nf][3] * iz1;
        float h2 = tf32f(t2), h3 = tf32f(t3);
        *(float4*)(Og + (size_t)(r0 + 8) * 128 + c2) =
            make_float4(h2, tf32f(t2 - h2), h3, tf32f(t3 - h3));
    }
}

// ---------------------------------------------------------------------------
// Launch: Q(0), K(1), V(2), fused(3 <- PROFILED), O(4)
// ---------------------------------------------------------------------------
extern "C" void kernel_launch(void* const* d_in, const int* in_sizes, int n_in,
                              void* d_out, int out_size)
{
    const float* x  = (const float*)d_in[0];
    const float* y  = (const float*)d_in[1];
    const float* Wq = (const float*)d_in[2];
    const float* bq = (const float*)d_in[3];
    const float* Wk = (const float*)d_in[4];
    const float* bk = (const float*)d_in[5];
    const float* Wv = (const float*)d_in[6];
    const float* bv = (const float*)d_in[7];
    const float* Wo = (const float*)d_in[8];
    const float* bo = (const float*)d_in[9];
    float* out = (float*)d_out;

    float *Qhl, *Khl, *Vp, *Ohl, *KsumP;
    cudaGetSymbolAddress((void**)&Qhl, g_Qhl);
    cudaGetSymbolAddress((void**)&Khl, g_Khl);
    cudaGetSymbolAddress((void**)&Vp, g_Vp);
    cudaGetSymbolAddress((void**)&Ohl, g_Ohl);
    cudaGetSymbolAddress((void**)&KsumP, g_Ksum);

    cudaFuncSetAttribute(fused_attn,
                         cudaFuncAttributeMaxDynamicSharedMemorySize, FUSED_SMEM);
    cudaFuncSetAttribute((gemm_t<4,0>),
                         cudaFuncAttributeMaxDynamicSharedMemorySize, GEMM_SMEM_BYTES);
    cudaFuncSetAttribute((gemm_t<0,1>),
                         cudaFuncAttributeMaxDynamicSharedMemorySize, GEMM_SMEM_BYTES);

    dim3 gProj(DMODEL / 128, MROWS / 128);   // (4, 64)

    sgemm_qk<0><<<gProj, 256>>>(x, Wq, bq, Qhl, KsumP);                 // 0: Q fp32-exact
    sgemm_qk<1><<<gProj, 256>>>(y, Wk, bk, Khl, KsumP);                 // 1: K fp32-exact + Ksum
    gemm_t<4,0><<<gProj, 256, GEMM_SMEM_BYTES>>>(y, Wv, bv, Vp);        // 2: V paired tf32
    fused_attn<<<dim3(16, NGROUP), 512, FUSED_SMEM>>>(Qhl, Khl, Vp, KsumP, Ohl); // 3 <- profiled
    gemm_t<0,1><<<gProj, 256, GEMM_SMEM_BYTES>>>(Ohl, Wo, bo, out);     // 4: O projection
}

// round 11
// speedup vs baseline: 1.0796x; 1.0796x over previous
#include <cuda_runtime.h>
#include <math.h>
#include <stdint.h>

#define SLEN   2048
#define DHEAD  64
#define NGROUP 32
#define MROWS  8192
#define DMODEL 512
#define QK_SCALE 0.04419417382415922f   // 1/sqrt(512)

// Scratch
__device__ float g_Qhl[(size_t)2 * MROWS * DMODEL];  // interleaved {hi,lo}, pre-scaled
__device__ float g_Khl[(size_t)2 * MROWS * DMODEL];  // interleaved {hi,lo}
__device__ float g_Vp [(size_t)MROWS * DMODEL];      // pair-transposed tf32
__device__ float g_Ohl[(size_t)2 * MROWS * DMODEL];  // interleaved {hi,lo}
__device__ float g_Ksum[NGROUP * DHEAD];

__device__ __forceinline__ uint32_t f32_to_tf32(float x) {
    uint32_t r;
    asm("cvt.rna.tf32.f32 %0, %1;" : "=r"(r) : "f"(x));
    return r;
}
__device__ __forceinline__ float tf32f(float x) {
    return __uint_as_float(f32_to_tf32(x));
}
__device__ __forceinline__ void mma_tf32(float (&c)[4],
    uint32_t a0, uint32_t a1, uint32_t a2, uint32_t a3,
    uint32_t b0, uint32_t b1)
{
    asm volatile(
        "mma.sync.aligned.m16n8k8.row.col.f32.tf32.tf32.f32 "
        "{%0,%1,%2,%3}, {%4,%5,%6,%7}, {%8,%9}, {%0,%1,%2,%3};\n"
        : "+f"(c[0]), "+f"(c[1]), "+f"(c[2]), "+f"(c[3])
        : "r"(a0), "r"(a1), "r"(a2), "r"(a3), "r"(b0), "r"(b1));
}

// ---------------------------------------------------------------------------
// fp32 FFMA SGEMM for Q and K projections (EXACT fp32 -> protects rel_err).
// MODE 0 (Q): t *= QK_SCALE, write interleaved {hi,lo}; block(0,0) zeroes Ksum.
// MODE 1 (K): write interleaved {hi,lo} + fused exact column-sum -> Ksum.
// ---------------------------------------------------------------------------
template<int MODE>
__global__ __launch_bounds__(256) void sgemm_qk(
    const float* __restrict__ A, const float* __restrict__ W,
    const float* __restrict__ bias, float* __restrict__ C,
    float* __restrict__ Ksum)
{
    __shared__ float As[8][128];
    __shared__ float Bs[8][128];
    __shared__ float s_cs[128];

    const int tid = threadIdx.x;
    const int bx = blockIdx.x, by = blockIdx.y;
    const float* Ab = A + (size_t)by * 128 * DMODEL;
    const float* Bb = W + bx * 128;

    const int arow = tid >> 1, acol = (tid & 1) * 4;
    const int brow = tid >> 5, bcol = (tid & 31) * 4;
    const int ty = tid >> 4, tx = tid & 15;

    if (MODE == 0 && bx == 0 && by == 0) {
        for (int i = tid; i < NGROUP * DHEAD; i += 256) Ksum[i] = 0.f;
    }
    if (MODE == 1 && tid < 128) s_cs[tid] = 0.f;

    float acc[8][8] = {};

    for (int k0 = 0; k0 < DMODEL; k0 += 8) {
        float4 av = *(const float4*)(Ab + (size_t)arow * DMODEL + k0 + acol);
        As[acol + 0][arow] = av.x;
        As[acol + 1][arow] = av.y;
        As[acol + 2][arow] = av.z;
        As[acol + 3][arow] = av.w;
        *(float4*)&Bs[brow][bcol] =
            *(const float4*)(Bb + (size_t)(k0 + brow) * DMODEL + bcol);
        __syncthreads();

        #pragma unroll
        for (int k = 0; k < 8; k++) {
            float a[8], b[8];
            *(float4*)&a[0] = *(float4*)&As[k][ty * 8];
            *(float4*)&a[4] = *(float4*)&As[k][ty * 8 + 4];
            *(float4*)&b[0] = *(float4*)&Bs[k][tx * 8];
            *(float4*)&b[4] = *(float4*)&Bs[k][tx * 8 + 4];
            #pragma unroll
            for (int i = 0; i < 8; i++)
                #pragma unroll
                for (int j = 0; j < 8; j++)
                    acc[i][j] += a[i] * b[j];
        }
        __syncthreads();
    }

    float cs[8];
    if (MODE == 1)
        #pragma unroll
        for (int j = 0; j < 8; j++) cs[j] = 0.f;

    #pragma unroll
    for (int i = 0; i < 8; i++) {
        int row = by * 128 + ty * 8 + i;
        #pragma unroll
        for (int j = 0; j < 8; j += 2) {
            int c = bx * 128 + tx * 8 + j;
            float t0 = acc[i][j]     + bias[c];
            float t1 = acc[i][j + 1] + bias[c + 1];
            if (MODE == 1) { cs[j] += t0; cs[j + 1] += t1; }
            if (MODE == 0) { t0 *= QK_SCALE; t1 *= QK_SCALE; }
            float h0 = tf32f(t0), h1 = tf32f(t1);
            *(float4*)(C + 2 * ((size_t)row * DMODEL + c)) =
                make_float4(h0, tf32f(t0 - h0), h1, tf32f(t1 - h1));
        }
    }

    if (MODE == 1) {
        #pragma unroll
        for (int j = 0; j < 8; j++)
            atomicAdd(&s_cs[tx * 8 + j], cs[j]);
        __syncthreads();
        if (tid < 128)
            atomicAdd(&Ksum[(by >> 1) * 64 + (tid & 63)], s_cs[tid]);
    }
}

// ---------------------------------------------------------------------------
// 3xtf32 GEMM for V and O projections.
// MODE 0: fp32 out. MODE 4: V pair-transposed tf32 out (per 128-key block:
//   [d][keypair], k and k+4 adjacent).
// ---------------------------------------------------------------------------
#define AS 133
#define BS 37
#define GEMM_SMEM_FLOATS (2 * 32 * AS + 2 * 128 * BS)
#define GEMM_SMEM_BYTES  (GEMM_SMEM_FLOATS * 4)

template<int MODE, int AHL>
__global__ __launch_bounds__(256, 2) void gemm_t(
    const float* __restrict__ A, const float* __restrict__ W,
    const float* __restrict__ bias, float* __restrict__ C)
{
    extern __shared__ float gsm[];
    float* AhiT = gsm;                       // [32][133]
    float* AloT = AhiT + 32 * AS;
    float* Bhi  = AloT + 32 * AS;            // [128][37]
    float* Blo  = Bhi + 128 * BS;

    const int tid = threadIdx.x;
    const int bx = blockIdx.x, by = blockIdx.y;
    const int warp = tid >> 5, lane = tid & 31;
    const int wm = warp >> 2, wn = warp & 3;
    const int lg = lane >> 2, la = lane & 3;

    float acc[4][4][4] = {};

    for (int k0 = 0; k0 < DMODEL; k0 += 32) {
        #pragma unroll
        for (int l = 0; l < 16; l++) {
            int idx = tid + l * 256;
            int r = idx >> 5, k = idx & 31;
            if (AHL) {
                float2 v = *(const float2*)(A +
                    2 * ((size_t)(by * 128 + r) * DMODEL + k0 + k));
                AhiT[k * AS + r] = v.x;
                AloT[k * AS + r] = v.y;
            } else {
                float v = A[(size_t)(by * 128 + r) * DMODEL + k0 + k];
                float h = tf32f(v);
                AhiT[k * AS + r] = h;
                AloT[k * AS + r] = tf32f(v - h);
            }
        }
        #pragma unroll
        for (int l = 0; l < 16; l++) {
            int idx = tid + l * 256;
            int k = idx >> 7, n = idx & 127;
            float b = W[(size_t)(k0 + k) * DMODEL + bx * 128 + n];
            float h = tf32f(b);
            Bhi[n * BS + k] = h;
            Blo[n * BS + k] = tf32f(b - h);
        }
        __syncthreads();

        #pragma unroll
        for (int kk = 0; kk < 4; kk++) {
            uint32_t ahi[4][4], alo[4][4];
            #pragma unroll
            for (int mf = 0; mf < 4; mf++) {
                int r0 = wm * 64 + mf * 16 + lg;
                int c0 = kk * 8 + la;
                ahi[mf][0] = __float_as_uint(AhiT[c0 * AS + r0]);
                ahi[mf][1] = __float_as_uint(AhiT[c0 * AS + r0 + 8]);
                ahi[mf][2] = __float_as_uint(AhiT[(c0 + 4) * AS + r0]);
                ahi[mf][3] = __float_as_uint(AhiT[(c0 + 4) * AS + r0 + 8]);
                alo[mf][0] = __float_as_uint(AloT[c0 * AS + r0]);
                alo[mf][1] = __float_as_uint(AloT[c0 * AS + r0 + 8]);
                alo[mf][2] = __float_as_uint(AloT[(c0 + 4) * AS + r0]);
                alo[mf][3] = __float_as_uint(AloT[(c0 + 4) * AS + r0 + 8]);
            }
            #pragma unroll
            for (int nf = 0; nf < 4; nf++) {
                int n = wn * 32 + nf * 8 + lg;
                int c0 = kk * 8 + la;
                uint32_t bhi0 = __float_as_uint(Bhi[n * BS + c0]);
                uint32_t bhi1 = __float_as_uint(Bhi[n * BS + c0 + 4]);
                uint32_t blo0 = __float_as_uint(Blo[n * BS + c0]);
                uint32_t blo1 = __float_as_uint(Blo[n * BS + c0 + 4]);
                #pragma unroll
                for (int mf = 0; mf < 4; mf++) {
                    mma_tf32(acc[mf][nf], ahi[mf][0], ahi[mf][1], ahi[mf][2], ahi[mf][3], bhi0, bhi1);
                    mma_tf32(acc[mf][nf], alo[mf][0], alo[mf][1], alo[mf][2], alo[mf][3], bhi0, bhi1);
                    mma_tf32(acc[mf][nf], ahi[mf][0], ahi[mf][1], ahi[mf][2], ahi[mf][3], blo0, blo1);
                }
            }
        }
        __syncthreads();
    }

    #pragma unroll
    for (int mf = 0; mf < 4; mf++) {
        #pragma unroll
        for (int h = 0; h < 2; h++) {
            int r = by * 128 + wm * 64 + mf * 16 + lg + h * 8;
            #pragma unroll
            for (int nf = 0; nf < 4; nf++) {
                int c = bx * 128 + wn * 32 + nf * 8 + 2 * la;
                float t0 = acc[mf][nf][2 * h + 0] + bias[c];
                float t1 = acc[mf][nf][2 * h + 1] + bias[c + 1];
                if (MODE == 0) {
                    *(float2*)(C + (size_t)r * DMODEL + c) = make_float2(t0, t1);
                } else {
                    int g  = r >> 8;
                    int kr = ((r & 255) << 3) + (c >> 6);
                    int d  = c & 63;
                    size_t base = (size_t)g * 131072 + (size_t)(kr >> 7) * 8192
                                + (size_t)d * 128;
                    int pi2 = (((kr & 127) >> 3) << 3) + ((kr & 3) << 1) + ((kr >> 2) & 1);
                    C[base + pi2]       = tf32f(t0);
                    C[base + 128 + pi2] = tf32f(t1);   // d+1
                }
            }
        }
    }
}

// ---------------------------------------------------------------------------
// Fused attention v6: 256 threads / 8 warps / block; block = 64 q-rows;
// 64-key tiles (32 iters); TWO blocks co-resident per SM (smem 108.5 KB).
// warp = (q-strip wq: 16 rows) x (key/d-half wk). K/V tiles prefetched into
// registers one tile ahead (gmem latency overlapped with S+PV).
// Strides: QS=KS=136 (conflict-free LDS.64 frags), Vs=72, Ps=76.
// ---------------------------------------------------------------------------
#define QS  136
#define KS  136
#define VTS 72
#define PSS 76
#define FUSED_SMEM ((64 * QS + 64 * KS + 64 * VTS + 64 * PSS + 64 + 64 + 128) * 4)

__global__ __launch_bounds__(256, 2) void fused_attn(
    const float* __restrict__ Qhl, const float* __restrict__ Khl,
    const float* __restrict__ Vp, const float* __restrict__ Ksum,
    float* __restrict__ Ohl)
{
    extern __shared__ float sm[];
    float* Qs     = sm;                    // [64][136] interleaved hi/lo
    float* KP     = Qs + 64 * QS;          // [64][136] K tile (64 keys, hi/lo)
    float* Vs     = KP + 64 * KS;          // [64 d][72] paired tf32
    float* Ps     = Vs + 64 * VTS;         // [64 q][76] tf32 probs
    float* s_ksum = Ps + 64 * PSS;         // 64
    float* s_mean = s_ksum + 64;           // 64
    float* zsm    = s_mean + 64;           // 128

    const int tid = threadIdx.x;
    const int lane = tid & 31, warp = tid >> 5;
    const int wq = warp >> 1, wk = warp & 1;
    const int lg = lane >> 2, la = lane & 3;
    const int g = blockIdx.y, qt = blockIdx.x;

    const float* Qg = Qhl + 2 * ((size_t)(g * SLEN + qt * 64)) * DHEAD;
    const float* Kg = Khl + 2 * (size_t)g * SLEN * DHEAD;
    const float* Vg = Vp + (size_t)g * SLEN * DHEAD;

    // per-thread tile-load coordinates
    const int kr_[2] = { tid >> 5, (tid + 256) >> 5 };   // rows per l-step (stride 8)
    const int kc_ = (tid & 31) * 4;
    const int vd_ = tid >> 4;                            // stride 16 per l-step
    const int vc_ = (tid & 15) * 4;

    // load Q tile: 2048 float4, 8/thread
    #pragma unroll
    for (int l = 0; l < 8; l++) {
        int idx = tid + l * 256;
        int r = idx >> 5, c = (idx & 31) * 4;
        *(float4*)(Qs + r * QS + c) = *(const float4*)(Qg + (size_t)r * 128 + c);
    }
    if (tid < 64) s_ksum[tid] = Ksum[g * 64 + tid];
    __syncthreads();
    if (tid < 64) {
        float a = 0.f;
        #pragma unroll
        for (int d = 0; d < 64; d++)
            a += (Qs[tid * QS + 2 * d] + Qs[tid * QS + 2 * d + 1]) * s_ksum[d];
        s_mean[tid] = a * (1.0f / 2048.0f);
    }
    __syncthreads();

    const int r0 = wq * 16 + lg;
    const float m0 = s_mean[r0], m1 = s_mean[r0 + 8];

    float oacc[4][4] = {};
    float z0 = 0.f, z1 = 0.f;

    // prefetch tile 0 into registers
    float4 kreg[8], vreg[4];
    #pragma unroll
    for (int l = 0; l < 8; l++)
        kreg[l] = *(const float4*)(Kg + (size_t)((l & 1 ? kr_[1] : kr_[0]) + (l >> 1) * 16) * 128 + kc_);
    #pragma unroll
    for (int l = 0; l < 4; l++)
        vreg[l] = *(const float4*)(Vg + (size_t)(vd_ + l * 16) * 128 + vc_);

    for (int kt = 0; kt < 32; kt++) {
        // store prefetched tile to smem
        #pragma unroll
        for (int l = 0; l < 8; l++) {
            int r = (l & 1 ? kr_[1] : kr_[0]) + (l >> 1) * 16;
            *(float4*)(KP + r * KS + kc_) = kreg[l];
        }
        #pragma unroll
        for (int l = 0; l < 4; l++)
            *(float4*)(Vs + (vd_ + l * 16) * VTS + vc_) = vreg[l];
        __syncthreads();

        // prefetch next tile (LDG in flight during S + PV)
        if (kt < 31) {
            const float* Kn = Kg + (size_t)(kt + 1) * 64 * 128;
            #pragma unroll
            for (int l = 0; l < 8; l++)
                kreg[l] = *(const float4*)(Kn + (size_t)((l & 1 ? kr_[1] : kr_[0]) + (l >> 1) * 16) * 128 + kc_);
            const float* Vn = Vg + (size_t)((kt + 1) >> 1) * 8192 + ((kt + 1) & 1) * 64;
            #pragma unroll
            for (int l = 0; l < 4; l++)
                vreg[l] = *(const float4*)(Vn + (size_t)(vd_ + l * 16) * 128 + vc_);
        }

        // === S = Q @ K^T (3xtf32): warp = 16 q-rows x 32 keys ===
        float sc[4][4] = {};
        #pragma unroll
        for (int kk = 0; kk < 8; kk++) {
            int c2 = 2 * (kk * 8 + la);
            float2 q0 = *(const float2*)(Qs + r0 * QS + c2);
            float2 q1 = *(const float2*)(Qs + (r0 + 8) * QS + c2);
            float2 q2 = *(const float2*)(Qs + r0 * QS + c2 + 8);
            float2 q3 = *(const float2*)(Qs + (r0 + 8) * QS + c2 + 8);
            uint32_t qh0 = __float_as_uint(q0.x), ql0 = __float_as_uint(q0.y);
            uint32_t qh1 = __float_as_uint(q1.x), ql1 = __float_as_uint(q1.y);
            uint32_t qh2 = __float_as_uint(q2.x), ql2 = __float_as_uint(q2.y);
            uint32_t qh3 = __float_as_uint(q3.x), ql3 = __float_as_uint(q3.y);
            #pragma unroll
            for (int nf = 0; nf < 4; nf++) {
                int kr = wk * 32 + nf * 8 + lg;
                float2 b0 = *(const float2*)(KP + kr * KS + c2);
                float2 b1 = *(const float2*)(KP + kr * KS + c2 + 8);
                uint32_t bh0 = __float_as_uint(b0.x), bh1 = __float_as_uint(b1.x);
                uint32_t bl0 = __float_as_uint(b0.y), bl1 = __float_as_uint(b1.y);
                mma_tf32(sc[nf], qh0, qh1, qh2, qh3, bh0, bh1);
                mma_tf32(sc[nf], ql0, ql1, ql2, ql3, bh0, bh1);
                mma_tf32(sc[nf], qh0, qh1, qh2, qh3, bl0, bl1);
            }
        }

        // === mask + exp; tf32 P -> Ps; Z from fp32 p ===
        #pragma unroll
        for (int nf = 0; nf < 4; nf++) {
            int col = wk * 32 + nf * 8 + 2 * la;
            float p0 = (sc[nf][0] > m0) ? __expf(sc[nf][0]) : 0.f;
            float p1 = (sc[nf][1] > m0) ? __expf(sc[nf][1]) : 0.f;
            float p2 = (sc[nf][2] > m1) ? __expf(sc[nf][2]) : 0.f;
            float p3 = (sc[nf][3] > m1) ? __expf(sc[nf][3]) : 0.f;
            z0 += p0 + p1; z1 += p2 + p3;
            *(float2*)(Ps + r0 * PSS + col)       = make_float2(tf32f(p0), tf32f(p1));
            *(float2*)(Ps + (r0 + 8) * PSS + col) = make_float2(tf32f(p2), tf32f(p3));
        }
        __syncthreads();   // P complete across k-half warps

        // === O += P @ V: warp = q-strip x 32 d-cols, 64 keys ===
        #pragma unroll
        for (int kk = 0; kk < 8; kk++) {
            int c0 = kk * 8 + la;
            uint32_t a0 = __float_as_uint(Ps[r0 * PSS + c0]);
            uint32_t a1 = __float_as_uint(Ps[(r0 + 8) * PSS + c0]);
            uint32_t a2 = __float_as_uint(Ps[r0 * PSS + c0 + 4]);
            uint32_t a3 = __float_as_uint(Ps[(r0 + 8) * PSS + c0 + 4]);
            int vp2 = kk * 8 + la * 2;
            #pragma unroll
            for (int nf = 0; nf < 4; nf++) {
                int vc = wk * 32 + nf * 8 + lg;
                float2 bv = *(const float2*)(Vs + vc * VTS + vp2);
                mma_tf32(oacc[nf], a0, a1, a2, a3,
                         __float_as_uint(bv.x), __float_as_uint(bv.y));
            }
        }
        __syncthreads();   // protect KP/Vs/Ps before next tile store
    }

    z0 += __shfl_xor_sync(0xffffffffu, z0, 1);
    z0 += __shfl_xor_sync(0xffffffffu, z0, 2);
    z1 += __shfl_xor_sync(0xffffffffu, z1, 1);
    z1 += __shfl_xor_sync(0xffffffffu, z1, 2);
    if (la == 0) {
        zsm[r0 * 2 + wk]       = z0;
        zsm[(r0 + 8) * 2 + wk] = z1;
    }
    __syncthreads();
    const float iz0 = 1.f / (zsm[r0 * 2] + zsm[r0 * 2 + 1]);
    const float iz1 = 1.f / (zsm[(r0 + 8) * 2] + zsm[(r0 + 8) * 2 + 1]);

    float* Og = Ohl + 2 * ((size_t)(g * SLEN + qt * 64)) * DHEAD;
    #pragma unroll
    for (int nf = 0; nf < 4; nf++) {
        int c2 = 2 * (wk * 32 + nf * 8 + 2 * la);
        float t0 = oacc[nf][0] * iz0, t1 = oacc[nf][1] * iz0;
        float h0 = tf32f(t0), h1 = tf32f(t1);
        *(float4*)(Og + (size_t)r0 * 128 + c2) =
            make_float4(h0, tf32f(t0 - h0), h1, tf32f(t1 - h1));
        float t2 = oacc[nf][2] * iz1, t3 = oacc[nf][3] * iz1;
        float h2 = tf32f(t2), h3 = tf32f(t3);
        *(float4*)(Og + (size_t)(r0 + 8) * 128 + c2) =
            make_float4(h2, tf32f(t2 - h2), h3, tf32f(t3 - h3));
    }
}

// ---------------------------------------------------------------------------
// Launch: Q(0), K(1), V(2), fused(3 <- PROFILED), O(4)
// ---------------------------------------------------------------------------
extern "C" void kernel_launch(void* const* d_in, const int* in_sizes, int n_in,
                              void* d_out, int out_size)
{
    const float* x  = (const float*)d_in[0];
    const float* y  = (const float*)d_in[1];
    const float* Wq = (const float*)d_in[2];
    const float* bq = (const float*)d_in[3];
    const float* Wk = (const float*)d_in[4];
    const float* bk = (const float*)d_in[5];
    const float* Wv = (const float*)d_in[6];
    const float* bv = (const float*)d_in[7];
    const float* Wo = (const float*)d_in[8];
    const float* bo = (const float*)d_in[9];
    float* out = (float*)d_out;

    float *Qhl, *Khl, *Vp, *Ohl, *KsumP;
    cudaGetSymbolAddress((void**)&Qhl, g_Qhl);
    cudaGetSymbolAddress((void**)&Khl, g_Khl);
    cudaGetSymbolAddress((void**)&Vp, g_Vp);
    cudaGetSymbolAddress((void**)&Ohl, g_Ohl);
    cudaGetSymbolAddress((void**)&KsumP, g_Ksum);

    cudaFuncSetAttribute(fused_attn,
                         cudaFuncAttributeMaxDynamicSharedMemorySize, FUSED_SMEM);
    cudaFuncSetAttribute((gemm_t<4,0>),
                         cudaFuncAttributeMaxDynamicSharedMemorySize, GEMM_SMEM_BYTES);
    cudaFuncSetAttribute((gemm_t<0,1>),
                         cudaFuncAttributeMaxDynamicSharedMemorySize, GEMM_SMEM_BYTES);

    dim3 gProj(DMODEL / 128, MROWS / 128);   // (4, 64)

    sgemm_qk<0><<<gProj, 256>>>(x, Wq, bq, Qhl, KsumP);                 // 0: Q fp32-exact
    sgemm_qk<1><<<gProj, 256>>>(y, Wk, bk, Khl, KsumP);                 // 1: K fp32-exact + Ksum
    gemm_t<4,0><<<gProj, 256, GEMM_SMEM_BYTES>>>(y, Wv, bv, Vp);        // 2: V paired tf32
    fused_attn<<<dim3(32, NGROUP), 256, FUSED_SMEM>>>(Qhl, Khl, Vp, KsumP, Ohl); // 3 <- profiled
    gemm_t<0,1><<<gProj, 256, GEMM_SMEM_BYTES>>>(Ohl, Wo, bo, out);     // 4: O projection
}

// round 13
// speedup vs baseline: 1.1714x; 1.0850x over previous
#include <cuda_runtime.h>
#include <math.h>
#include <stdint.h>

#define SLEN   2048
#define DHEAD  64
#define NGROUP 32
#define MROWS  8192
#define DMODEL 512
#define QK_SCALE 0.04419417382415922f   // 1/sqrt(512)

// Scratch
// Q/K: paired-split layout. Per 64-elem head row (128 floats): for kk=0..7,
// la=0..3, float4 at kk*16+la*4 = {hi(e), lo(e), hi(e+4), lo(e+4)}, e=kk*8+la.
__device__ float g_Qhl[(size_t)2 * MROWS * DMODEL];  // pre-scaled by QK_SCALE
__device__ float g_Khl[(size_t)2 * MROWS * DMODEL];
__device__ float g_Vp [(size_t)MROWS * DMODEL];      // pair-transposed tf32
__device__ float g_Ohl[(size_t)2 * MROWS * DMODEL];  // interleaved {hi,lo}, natural order
__device__ float g_Ksum[NGROUP * DHEAD];

__device__ __forceinline__ uint32_t f32_to_tf32(float x) {
    uint32_t r;
    asm("cvt.rna.tf32.f32 %0, %1;" : "=r"(r) : "f"(x));
    return r;
}
__device__ __forceinline__ float tf32f(float x) {
    return __uint_as_float(f32_to_tf32(x));
}
__device__ __forceinline__ void mma_tf32(float (&c)[4],
    uint32_t a0, uint32_t a1, uint32_t a2, uint32_t a3,
    uint32_t b0, uint32_t b1)
{
    asm volatile(
        "mma.sync.aligned.m16n8k8.row.col.f32.tf32.tf32.f32 "
        "{%0,%1,%2,%3}, {%4,%5,%6,%7}, {%8,%9}, {%0,%1,%2,%3};\n"
        : "+f"(c[0]), "+f"(c[1]), "+f"(c[2]), "+f"(c[3])
        : "r"(a0), "r"(a1), "r"(a2), "r"(a3), "r"(b0), "r"(b1));
}
__device__ __forceinline__ uint32_t smem_u32(const void* p) {
    uint32_t r;
    asm("{ .reg .u64 t; cvta.to.shared.u64 t, %1; cvt.u32.u64 %0, t; }"
        : "=r"(r) : "l"(p));
    return r;
}
#define CP_ASYNC16(dst, src) \
    asm volatile("cp.async.cg.shared.global [%0], [%1], 16;" :: "r"(dst), "l"(src))
#define CP_COMMIT() asm volatile("cp.async.commit_group;" ::: "memory")
#define CP_WAIT0()  asm volatile("cp.async.wait_group 0;" ::: "memory")

// ---------------------------------------------------------------------------
// fp32 FFMA SGEMM for Q and K projections (EXACT fp32 -> protects rel_err).
// Epilogue writes the PAIRED hi/lo layout (see top).
// MODE 0 (Q): t *= QK_SCALE; block(0,0) zeroes Ksum.
// MODE 1 (K): + fused exact column-sum -> Ksum.
// ---------------------------------------------------------------------------
template<int MODE>
__global__ __launch_bounds__(256) void sgemm_qk(
    const float* __restrict__ A, const float* __restrict__ W,
    const float* __restrict__ bias, float* __restrict__ C,
    float* __restrict__ Ksum)
{
    __shared__ float As[8][128];
    __shared__ float Bs[8][128];
    __shared__ float s_cs[128];

    const int tid = threadIdx.x;
    const int bx = blockIdx.x, by = blockIdx.y;
    const float* Ab = A + (size_t)by * 128 * DMODEL;
    const float* Bb = W + bx * 128;

    const int arow = tid >> 1, acol = (tid & 1) * 4;
    const int brow = tid >> 5, bcol = (tid & 31) * 4;
    const int ty = tid >> 4, tx = tid & 15;

    if (MODE == 0 && bx == 0 && by == 0) {
        for (int i = tid; i < NGROUP * DHEAD; i += 256) Ksum[i] = 0.f;
    }
    if (MODE == 1 && tid < 128) s_cs[tid] = 0.f;

    float acc[8][8] = {};

    for (int k0 = 0; k0 < DMODEL; k0 += 8) {
        float4 av = *(const float4*)(Ab + (size_t)arow * DMODEL + k0 + acol);
        As[acol + 0][arow] = av.x;
        As[acol + 1][arow] = av.y;
        As[acol + 2][arow] = av.z;
        As[acol + 3][arow] = av.w;
        *(float4*)&Bs[brow][bcol] =
            *(const float4*)(Bb + (size_t)(k0 + brow) * DMODEL + bcol);
        __syncthreads();

        #pragma unroll
        for (int k = 0; k < 8; k++) {
            float a[8], b[8];
            *(float4*)&a[0] = *(float4*)&As[k][ty * 8];
            *(float4*)&a[4] = *(float4*)&As[k][ty * 8 + 4];
            *(float4*)&b[0] = *(float4*)&Bs[k][tx * 8];
            *(float4*)&b[4] = *(float4*)&Bs[k][tx * 8 + 4];
            #pragma unroll
            for (int i = 0; i < 8; i++)
                #pragma unroll
                for (int j = 0; j < 8; j++)
                    acc[i][j] += a[i] * b[j];
        }
        __syncthreads();
    }

    float cs[8];
    if (MODE == 1)
        #pragma unroll
        for (int j = 0; j < 8; j++) cs[j] = 0.f;

    #pragma unroll
    for (int i = 0; i < 8; i++) {
        int row = by * 128 + ty * 8 + i;
        #pragma unroll
        for (int j = 0; j < 8; j += 2) {
            int c = bx * 128 + tx * 8 + j;
            float t0 = acc[i][j]     + bias[c];
            float t1 = acc[i][j + 1] + bias[c + 1];
            if (MODE == 1) { cs[j] += t0; cs[j + 1] += t1; }
            if (MODE == 0) { t0 *= QK_SCALE; t1 *= QK_SCALE; }
            float h0 = tf32f(t0), h1 = tf32f(t1);
            // paired layout: e0 = (tx&7)*8 + j; slot = kk*16 + (j&3)*4 + ((j>>2)&1)*2
            int sh = (tx & 7) * 16 + (j & 3) * 4 + ((j >> 2) & 1) * 2;
            float* seg = C + 2 * ((size_t)row * DMODEL + (c & ~63));
            *(float2*)(seg + sh)     = make_float2(h0, tf32f(t0 - h0));
            *(float2*)(seg + sh + 4) = make_float2(h1, tf32f(t1 - h1));
        }
    }

    if (MODE == 1) {
        #pragma unroll
        for (int j = 0; j < 8; j++)
            atomicAdd(&s_cs[tx * 8 + j], cs[j]);
        __syncthreads();
        if (tid < 128)
            atomicAdd(&Ksum[(by >> 1) * 64 + (tid & 63)], s_cs[tid]);
    }
}

// ---------------------------------------------------------------------------
// 3xtf32 GEMM for V and O projections (unchanged from R11).
// MODE 0: fp32 out. MODE 4: V pair-transposed tf32 out.
// ---------------------------------------------------------------------------
#define AS 133
#define BS 37
#define GEMM_SMEM_FLOATS (2 * 32 * AS + 2 * 128 * BS)
#define GEMM_SMEM_BYTES  (GEMM_SMEM_FLOATS * 4)

template<int MODE, int AHL>
__global__ __launch_bounds__(256, 2) void gemm_t(
    const float* __restrict__ A, const float* __restrict__ W,
    const float* __restrict__ bias, float* __restrict__ C)
{
    extern __shared__ float gsm[];
    float* AhiT = gsm;                       // [32][133]
    float* AloT = AhiT + 32 * AS;
    float* Bhi  = AloT + 32 * AS;            // [128][37]
    float* Blo  = Bhi + 128 * BS;

    const int tid = threadIdx.x;
    const int bx = blockIdx.x, by = blockIdx.y;
    const int warp = tid >> 5, lane = tid & 31;
    const int wm = warp >> 2, wn = warp & 3;
    const int lg = lane >> 2, la = lane & 3;

    float acc[4][4][4] = {};

    for (int k0 = 0; k0 < DMODEL; k0 += 32) {
        #pragma unroll
        for (int l = 0; l < 16; l++) {
            int idx = tid + l * 256;
            int r = idx >> 5, k = idx & 31;
            if (AHL) {
                // O path reads natural interleaved {hi,lo}
                float2 v = *(const float2*)(A +
                    2 * ((size_t)(by * 128 + r) * DMODEL + k0 + k));
                AhiT[k * AS + r] = v.x;
                AloT[k * AS + r] = v.y;
            } else {
                float v = A[(size_t)(by * 128 + r) * DMODEL + k0 + k];
                float h = tf32f(v);
                AhiT[k * AS + r] = h;
                AloT[k * AS + r] = tf32f(v - h);
            }
        }
        #pragma unroll
        for (int l = 0; l < 16; l++) {
            int idx = tid + l * 256;
            int k = idx >> 7, n = idx & 127;
            float b = W[(size_t)(k0 + k) * DMODEL + bx * 128 + n];
            float h = tf32f(b);
            Bhi[n * BS + k] = h;
            Blo[n * BS + k] = tf32f(b - h);
        }
        __syncthreads();

        #pragma unroll
        for (int kk = 0; kk < 4; kk++) {
            uint32_t ahi[4][4], alo[4][4];
            #pragma unroll
            for (int mf = 0; mf < 4; mf++) {
                int r0 = wm * 64 + mf * 16 + lg;
                int c0 = kk * 8 + la;
                ahi[mf][0] = __float_as_uint(AhiT[c0 * AS + r0]);
                ahi[mf][1] = __float_as_uint(AhiT[c0 * AS + r0 + 8]);
                ahi[mf][2] = __float_as_uint(AhiT[(c0 + 4) * AS + r0]);
                ahi[mf][3] = __float_as_uint(AhiT[(c0 + 4) * AS + r0 + 8]);
                alo[mf][0] = __float_as_uint(AloT[c0 * AS + r0]);
                alo[mf][1] = __float_as_uint(AloT[c0 * AS + r0 + 8]);
                alo[mf][2] = __float_as_uint(AloT[(c0 + 4) * AS + r0]);
                alo[mf][3] = __float_as_uint(AloT[(c0 + 4) * AS + r0 + 8]);
            }
            #pragma unroll
            for (int nf = 0; nf < 4; nf++) {
                int n = wn * 32 + nf * 8 + lg;
                int c0 = kk * 8 + la;
                uint32_t bhi0 = __float_as_uint(Bhi[n * BS + c0]);
                uint32_t bhi1 = __float_as_uint(Bhi[n * BS + c0 + 4]);
                uint32_t blo0 = __float_as_uint(Blo[n * BS + c0]);
                uint32_t blo1 = __float_as_uint(Blo[n * BS + c0 + 4]);
                #pragma unroll
                for (int mf = 0; mf < 4; mf++) {
                    mma_tf32(acc[mf][nf], ahi[mf][0], ahi[mf][1], ahi[mf][2], ahi[mf][3], bhi0, bhi1);
                    mma_tf32(acc[mf][nf], alo[mf][0], alo[mf][1], alo[mf][2], alo[mf][3], bhi0, bhi1);
                    mma_tf32(acc[mf][nf], ahi[mf][0], ahi[mf][1], ahi[mf][2], ahi[mf][3], blo0, blo1);
                }
            }
        }
        __syncthreads();
    }

    #pragma unroll
    for (int mf = 0; mf < 4; mf++) {
        #pragma unroll
        for (int h = 0; h < 2; h++) {
            int r = by * 128 + wm * 64 + mf * 16 + lg + h * 8;
            #pragma unroll
            for (int nf = 0; nf < 4; nf++) {
                int c = bx * 128 + wn * 32 + nf * 8 + 2 * la;
                float t0 = acc[mf][nf][2 * h + 0] + bias[c];
                float t1 = acc[mf][nf][2 * h + 1] + bias[c + 1];
                if (MODE == 0) {
                    *(float2*)(C + (size_t)r * DMODEL + c) = make_float2(t0, t1);
                } else {
                    int g  = r >> 8;
                    int kr = ((r & 255) << 3) + (c >> 6);
                    int d  = c & 63;
                    size_t base = (size_t)g * 131072 + (size_t)(kr >> 7) * 8192
                                + (size_t)d * 128;
                    int pi2 = (((kr & 127) >> 3) << 3) + ((kr & 3) << 1) + ((kr >> 2) & 1);
                    C[base + pi2]       = tf32f(t0);
                    C[base + 128 + pi2] = tf32f(t1);   // d+1
                }
            }
        }
    }
}

// ---------------------------------------------------------------------------
// Fused attention v7: 256 thr / 8 warps / block; block = 64 q-rows; 64-key
// tiles (32 iters); 2 blocks/SM. Q frags LIVE IN REGISTERS (paired gmem
// load, once). K/V tiles via cp.async (K issued during PV). K smem paired
// (one LDS.128 per B-frag, KS=144 conflict-free). P stored (k,k+4)-paired
// tf32 (PSS=72, conflict-free LDS.64 A-frags). V paired (VTS=72).
// Z summed from fp32 p.
// ---------------------------------------------------------------------------
#define KS  144
#define VTS 72
#define PSS 72
#define FUSED_SMEM ((64 * KS + 64 * VTS + 64 * PSS + 64 + 64 + 128) * 4)

__global__ __launch_bounds__(256, 2) void fused_attn(
    const float* __restrict__ Qhl, const float* __restrict__ Khl,
    const float* __restrict__ Vp, const float* __restrict__ Ksum,
    float* __restrict__ Ohl)
{
    extern __shared__ float sm[];
    float* Ks     = sm;                    // [64][144] paired K tile
    float* Vs     = Ks + 64 * KS;          // [64 d][72] paired V tile
    float* Ps     = Vs + 64 * VTS;         // [64 q][72] paired tf32 P
    float* s_ksum = Ps + 64 * PSS;         // 64
    float* s_mean = s_ksum + 64;           // 64
    float* zsm    = s_mean + 64;           // 128

    const int tid = threadIdx.x;
    const int lane = tid & 31, warp = tid >> 5;
    const int wq = warp >> 1, wk = warp & 1;
    const int lg = lane >> 2, la = lane & 3;
    const int g = blockIdx.y, qt = blockIdx.x;

    const float* Qg = Qhl + 2 * ((size_t)(g * SLEN + qt * 64)) * DHEAD;
    const float* Kg = Khl + 2 * (size_t)g * SLEN * DHEAD;
    const float* Vg = Vp + (size_t)g * SLEN * DHEAD;

    const uint32_t ks_u = smem_u32(Ks);
    const uint32_t vs_u = smem_u32(Vs);
    const int kr_c = tid >> 5, kc_c = (tid & 31) * 4;   // K copy coords
    const int vr_c = tid >> 4, vc_c = (tid & 15) * 4;   // V copy coords

    // issue tile 0 loads
    #pragma unroll
    for (int l = 0; l < 8; l++) {
        int r = kr_c + l * 8;
        CP_ASYNC16(ks_u + (uint32_t)(r * KS + kc_c) * 4,
                   Kg + (size_t)r * 128 + kc_c);
    }
    #pragma unroll
    for (int l = 0; l < 4; l++) {
        int d = vr_c + l * 16;
        CP_ASYNC16(vs_u + (uint32_t)(d * VTS + vc_c) * 4,
                   Vg + (size_t)d * 128 + vc_c);
    }
    CP_COMMIT();

    if (tid < 64) s_ksum[tid] = Ksum[g * 64 + tid];

    // Q fragments in registers (paired layout: one float4 = hi,lo,hi+4,lo+4)
    uint32_t qh[8][4], ql[8][4];
    const int r0 = wq * 16 + lg;
    #pragma unroll
    for (int kk = 0; kk < 8; kk++) {
        float4 v0 = *(const float4*)(Qg + (size_t)r0 * 128 + kk * 16 + la * 4);
        float4 v1 = *(const float4*)(Qg + (size_t)(r0 + 8) * 128 + kk * 16 + la * 4);
        qh[kk][0] = __float_as_uint(v0.x); ql[kk][0] = __float_as_uint(v0.y);
        qh[kk][2] = __float_as_uint(v0.z); ql[kk][2] = __float_as_uint(v0.w);
        qh[kk][1] = __float_as_uint(v1.x); ql[kk][1] = __float_as_uint(v1.y);
        qh[kk][3] = __float_as_uint(v1.z); ql[kk][3] = __float_as_uint(v1.w);
    }
    __syncthreads();   // s_ksum visible

    if (tid < 64) {
        const float* qr = Qg + (size_t)tid * 128;
        float a = 0.f;
        #pragma unroll
        for (int kk = 0; kk < 8; kk++)
            #pragma unroll
            for (int l2 = 0; l2 < 4; l2++) {
                float4 v = *(const float4*)(qr + kk * 16 + l2 * 4);
                a += (v.x + v.y) * s_ksum[kk * 8 + l2]
                   + (v.z + v.w) * s_ksum[kk * 8 + l2 + 4];
            }
        s_mean[tid] = a * (1.0f / 2048.0f);
    }
    CP_WAIT0();
    __syncthreads();   // s_mean + tile 0 ready

    const float m0 = s_mean[r0], m1 = s_mean[r0 + 8];
    const int s0 = (la >> 1) + ((la & 1) << 2);   // paired P write slot

    float oacc[4][4] = {};
    float z0 = 0.f, z1 = 0.f;

    for (int kt = 0; kt < 32; kt++) {
        if (kt > 0) { CP_WAIT0(); __syncthreads(); }

        // === S = Q @ K^T (3xtf32): warp = 16 q x 32 keys; Q from regs ===
        float sc[4][4] = {};
        #pragma unroll
        for (int kk = 0; kk < 8; kk++) {
            #pragma unroll
            for (int nf = 0; nf < 4; nf++) {
                int kr = wk * 32 + nf * 8 + lg;
                float4 b = *(const float4*)(Ks + kr * KS + kk * 16 + la * 4);
                uint32_t bh0 = __float_as_uint(b.x), bl0 = __float_as_uint(b.y);
                uint32_t bh1 = __float_as_uint(b.z), bl1 = __float_as_uint(b.w);
                mma_tf32(sc[nf], qh[kk][0], qh[kk][1], qh[kk][2], qh[kk][3], bh0, bh1);
                mma_tf32(sc[nf], ql[kk][0], ql[kk][1], ql[kk][2], ql[kk][3], bh0, bh1);
                mma_tf32(sc[nf], qh[kk][0], qh[kk][1], qh[kk][2], qh[kk][3], bl0, bl1);
            }
        }

        // === mask + exp; paired tf32 P; Z from fp32 p ===
        #pragma unroll
        for (int nf = 0; nf < 4; nf++) {
            int base = wk * 32 + nf * 8;
            float p0 = (sc[nf][0] > m0) ? __expf(sc[nf][0]) : 0.f;
            float p1 = (sc[nf][1] > m0) ? __expf(sc[nf][1]) : 0.f;
            float p2 = (sc[nf][2] > m1) ? __expf(sc[nf][2]) : 0.f;
            float p3 = (sc[nf][3] > m1) ? __expf(sc[nf][3]) : 0.f;
            z0 += p0 + p1; z1 += p2 + p3;
            Ps[r0 * PSS + base + s0]           = tf32f(p0);
            Ps[r0 * PSS + base + s0 + 2]       = tf32f(p1);
            Ps[(r0 + 8) * PSS + base + s0]     = tf32f(p2);
            Ps[(r0 + 8) * PSS + base + s0 + 2] = tf32f(p3);
        }
        __syncthreads();   // P complete; K reads done

        // K(kt+1) load overlaps PV
        if (kt < 31) {
            const float* Kn = Kg + (size_t)(kt + 1) * 64 * 128;
            #pragma unroll
            for (int l = 0; l < 8; l++) {
                int r = kr_c + l * 8;
                CP_ASYNC16(ks_u + (uint32_t)(r * KS + kc_c) * 4,
                           Kn + (size_t)r * 128 + kc_c);
            }
        }

        // === O += P @ V: warp = q-strip x 32 d-cols, 64 keys ===
        #pragma unroll
        for (int kk = 0; kk < 8; kk++) {
            float2 pa0 = *(const float2*)(Ps + r0 * PSS + kk * 8 + 2 * la);
            float2 pa1 = *(const float2*)(Ps + (r0 + 8) * PSS + kk * 8 + 2 * la);
            uint32_t a0 = __float_as_uint(pa0.x), a2 = __float_as_uint(pa0.y);
            uint32_t a1 = __float_as_uint(pa1.x), a3 = __float_as_uint(pa1.y);
            #pragma unroll
            for (int nf = 0; nf < 4; nf++) {
                int vc = wk * 32 + nf * 8 + lg;
                float2 bv = *(const float2*)(Vs + vc * VTS + kk * 8 + 2 * la);
                mma_tf32(oacc[nf], a0, a1, a2, a3,
                         __float_as_uint(bv.x), __float_as_uint(bv.y));
            }
        }
        __syncthreads();   // V/P reads done

        if (kt < 31) {
            const float* Vn = Vg + (size_t)((kt + 1) >> 1) * 8192 + ((kt + 1) & 1) * 64;
            #pragma unroll
            for (int l = 0; l < 4; l++) {
                int d = vr_c + l * 16;
                CP_ASYNC16(vs_u + (uint32_t)(d * VTS + vc_c) * 4,
                           Vn + (size_t)d * 128 + vc_c);
            }
            CP_COMMIT();
        }
    }

    z0 += __shfl_xor_sync(0xffffffffu, z0, 1);
    z0 += __shfl_xor_sync(0xffffffffu, z0, 2);
    z1 += __shfl_xor_sync(0xffffffffu, z1, 1);
    z1 += __shfl_xor_sync(0xffffffffu, z1, 2);
    if (la == 0) {
        zsm[r0 * 2 + wk]       = z0;
        zsm[(r0 + 8) * 2 + wk] = z1;
    }
    __syncthreads();
    const float iz0 = 1.f / (zsm[r0 * 2] + zsm[r0 * 2 + 1]);
    const float iz1 = 1.f / (zsm[(r0 + 8) * 2] + zsm[(r0 + 8) * 2 + 1]);

    // normalize + split hi/lo + write natural interleaved O
    float* Og = Ohl + 2 * ((size_t)(g * SLEN + qt * 64)) * DHEAD;
    #pragma unroll
    for (int nf = 0; nf < 4; nf++) {
        int c2 = 2 * (wk * 32 + nf * 8 + 2 * la);
        float t0 = oacc[nf][0] * iz0, t1 = oacc[nf][1] * iz0;
        float h0 = tf32f(t0), h1 = tf32f(t1);
        *(float4*)(Og + (size_t)r0 * 128 + c2) =
            make_float4(h0, tf32f(t0 - h0), h1, tf32f(t1 - h1));
        float t2 = oacc[nf][2] * iz1, t3 = oacc[nf][3] * iz1;
        float h2 = tf32f(t2), h3 = tf32f(t3);
        *(float4*)(Og + (size_t)(r0 + 8) * 128 + c2) =
            make_float4(h2, tf32f(t2 - h2), h3, tf32f(t3 - h3));
    }
}

// ---------------------------------------------------------------------------
// Launch: Q(0), K(1), V(2), fused(3 <- PROFILED), O(4)
// ---------------------------------------------------------------------------
extern "C" void kernel_launch(void* const* d_in, const int* in_sizes, int n_in,
                              void* d_out, int out_size)
{
    const float* x  = (const float*)d_in[0];
    const float* y  = (const float*)d_in[1];
    const float* Wq = (const float*)d_in[2];
    const float* bq = (const float*)d_in[3];
    const float* Wk = (const float*)d_in[4];
    const float* bk = (const float*)d_in[5];
    const float* Wv = (const float*)d_in[6];
    const float* bv = (const float*)d_in[7];
    const float* Wo = (const float*)d_in[8];
    const float* bo = (const float*)d_in[9];
    float* out = (float*)d_out;

    float *Qhl, *Khl, *Vp, *Ohl, *KsumP;
    cudaGetSymbolAddress((void**)&Qhl, g_Qhl);
    cudaGetSymbolAddress((void**)&Khl, g_Khl);
    cudaGetSymbolAddress((void**)&Vp, g_Vp);
    cudaGetSymbolAddress((void**)&Ohl, g_Ohl);
    cudaGetSymbolAddress((void**)&KsumP, g_Ksum);

    cudaFuncSetAttribute(fused_attn,
                         cudaFuncAttributeMaxDynamicSharedMemorySize, FUSED_SMEM);
    cudaFuncSetAttribute((gemm_t<4,0>),
                         cudaFuncAttributeMaxDynamicSharedMemorySize, GEMM_SMEM_BYTES);
    cudaFuncSetAttribute((gemm_t<0,1>),
                         cudaFuncAttributeMaxDynamicSharedMemorySize, GEMM_SMEM_BYTES);

    dim3 gProj(DMODEL / 128, MROWS / 128);   // (4, 64)

    sgemm_qk<0><<<gProj, 256>>>(x, Wq, bq, Qhl, KsumP);                 // 0: Q fp32-exact
    sgemm_qk<1><<<gProj, 256>>>(y, Wk, bk, Khl, KsumP);                 // 1: K fp32-exact + Ksum
    gemm_t<4,0><<<gProj, 256, GEMM_SMEM_BYTES>>>(y, Wv, bv, Vp);        // 2: V paired tf32
    fused_attn<<<dim3(32, NGROUP), 256, FUSED_SMEM>>>(Qhl, Khl, Vp, KsumP, Ohl); // 3 <- profiled
    gemm_t<0,1><<<gProj, 256, GEMM_SMEM_BYTES>>>(Ohl, Wo, bo, out);     // 4: O projection
}